// round 1
// baseline (speedup 1.0000x reference)
#include <cuda_runtime.h>
#include <math.h>

#define BATCH 32
#define LSEQ  512
#define DDIM  768

#define BM 64
#define BN 64
#define BK 16

// scratch for per-token weights (no cudaMalloc allowed)
__device__ float g_w[BATCH * LSEQ];

// ---------------------------------------------------------------------------
// Kernel 1: w[b,l] = sqrt(1e-5 + sum_d x[b,l,d]^2)
// one warp per row, float4 loads, shuffle reduction
// ---------------------------------------------------------------------------
__global__ void weight_kernel(const float* __restrict__ x) {
    int row  = blockIdx.x * 8 + (threadIdx.x >> 5);   // b*LSEQ + l
    int lane = threadIdx.x & 31;
    const float4* p = (const float4*)(x + (size_t)row * DDIM);
    float s = 0.f;
#pragma unroll
    for (int i = 0; i < DDIM / 4 / 32; i++) {         // 6 iters
        float4 v = p[lane + 32 * i];
        s += v.x * v.x + v.y * v.y + v.z * v.z + v.w * v.w;
    }
#pragma unroll
    for (int o = 16; o; o >>= 1) s += __shfl_xor_sync(0xffffffffu, s, o);
    if (lane == 0) g_w[row] = sqrtf(1e-5f + s);
}

// ---------------------------------------------------------------------------
// Kernel 2: per-batch C = A^T diag(w) A, 64x64 tiles, symmetric (tj>=ti only,
// mirror written via smem transpose stage so all global stores are coalesced)
// ---------------------------------------------------------------------------
__global__ __launch_bounds__(256)
void gram_kernel(const float* __restrict__ x, float* __restrict__ out) {
    const int tj = blockIdx.x;           // column tile (e)
    const int ti = blockIdx.y;           // row tile (d)
    const int b  = blockIdx.z;
    if (tj < ti) return;                 // symmetry: skip lower tiles

    __shared__ float As[BK][BM];         // w-scaled
    __shared__ float Bs[BK][BN];
    __shared__ float Ts[BN][BM + 4];     // transpose staging (+pad)

    const int tid = threadIdx.x;
    const int tx  = tid & 15;            // 0..15  -> n micro-tile
    const int ty  = tid >> 4;            // 0..15  -> m micro-tile

    const int lk = tid >> 4;             // k row this thread loads (0..15)
    const int lc = (tid & 15) * 4;       // float column this thread loads

    const float* xb = x + (size_t)b * LSEQ * DDIM;
    float*       ob = out + (size_t)b * DDIM * DDIM;

    float acc[4][4] = {};

    for (int k0 = 0; k0 < LSEQ; k0 += BK) {
        const int l = k0 + lk;
        const float w = g_w[b * LSEQ + l];
        float4 av = *(const float4*)(xb + (size_t)l * DDIM + ti * BM + lc);
        float4 bv = *(const float4*)(xb + (size_t)l * DDIM + tj * BN + lc);
        av.x *= w; av.y *= w; av.z *= w; av.w *= w;

        __syncthreads();                 // previous iteration's reads done
        *(float4*)&As[lk][lc] = av;
        *(float4*)&Bs[lk][lc] = bv;
        __syncthreads();

#pragma unroll
        for (int k = 0; k < BK; k++) {
            float4 a = *(const float4*)&As[k][ty * 4];
            float4 c = *(const float4*)&Bs[k][tx * 4];
            float am[4] = {a.x, a.y, a.z, a.w};
            float bn[4] = {c.x, c.y, c.z, c.w};
#pragma unroll
            for (int i = 0; i < 4; i++)
#pragma unroll
                for (int j = 0; j < 4; j++)
                    acc[i][j] = fmaf(am[i], bn[j], acc[i][j]);
        }
    }

    // direct (upper / diagonal) write — coalesced float4
#pragma unroll
    for (int i = 0; i < 4; i++) {
        int d = ti * BM + ty * 4 + i;
        float4 v = make_float4(acc[i][0], acc[i][1], acc[i][2], acc[i][3]);
        *(float4*)(ob + (size_t)d * DDIM + tj * BN + tx * 4) = v;
    }

    if (ti != tj) {
        // stage transpose in smem, then coalesced write of the mirror tile
#pragma unroll
        for (int i = 0; i < 4; i++)
#pragma unroll
            for (int j = 0; j < 4; j++)
                Ts[tx * 4 + j][ty * 4 + i] = acc[i][j];
        __syncthreads();
#pragma unroll
        for (int r4 = 0; r4 < 4; r4++) {
            int r = (tid >> 4) + r4 * 16;        // 0..63 (e-local row)
            int c = (tid & 15) * 4;              // d-local col
            float4 v = make_float4(Ts[r][c], Ts[r][c + 1], Ts[r][c + 2], Ts[r][c + 3]);
            *(float4*)(ob + (size_t)(tj * BN + r) * DDIM + ti * BM + c) = v;
        }
    }
}

// ---------------------------------------------------------------------------
extern "C" void kernel_launch(void* const* d_in, const int* in_sizes, int n_in,
                              void* d_out, int out_size) {
    const float* x = (const float*)d_in[0];
    float* out = (float*)d_out;

    weight_kernel<<<BATCH * LSEQ / 8, 256>>>(x);

    dim3 grid(DDIM / BN, DDIM / BM, BATCH);      // (12, 12, 32)
    gram_kernel<<<grid, 256>>>(x, out);
}

// round 3
// speedup vs baseline: 1.4173x; 1.4173x over previous
#include <cuda_runtime.h>
#include <cuda_bf16.h>
#include <cstdint>
#include <math.h>

#define BATCH 32
#define LSEQ  512
#define DDIM  768

// scratch (no cudaMalloc allowed)
__device__ float          g_sw [BATCH * LSEQ];
__device__ __nv_bfloat16  g_yhi[(size_t)BATCH * DDIM * LSEQ];
__device__ __nv_bfloat16  g_ylo[(size_t)BATCH * DDIM * LSEQ];

// ---------------------------------------------------------------------------
__device__ __forceinline__ uint32_t smem_u32(const void* p) {
    uint32_t a;
    asm("{ .reg .u64 t; cvta.to.shared.u64 t, %1; cvt.u32.u64 %0, t; }" : "=r"(a) : "l"(p));
    return a;
}

// 128 logical rows x 32 bf16 (64B); pack 2 rows per 128B physical row, XOR swizzle
__device__ __forceinline__ uint32_t sw_off(int r, int c) {
    uint32_t pr = (uint32_t)r >> 1;
    uint32_t ch = (uint32_t)(((r & 1) << 2) + c) ^ (pr & 7u);
    return pr * 128u + ch * 16u;
}

#define CP_ASYNC16(dst, src) \
    asm volatile("cp.async.cg.shared.global [%0], [%1], 16;" :: "r"(dst), "l"(src))
#define CP_COMMIT() asm volatile("cp.async.commit_group;" ::: "memory")
#define CP_WAIT1()  asm volatile("cp.async.wait_group 1;" ::: "memory")
#define CP_WAIT0()  asm volatile("cp.async.wait_group 0;" ::: "memory")

__device__ __forceinline__ void ldsm4(uint32_t* r, uint32_t a) {
    asm volatile("ldmatrix.sync.aligned.m8n8.x4.shared.b16 {%0,%1,%2,%3}, [%4];"
                 : "=r"(r[0]), "=r"(r[1]), "=r"(r[2]), "=r"(r[3]) : "r"(a));
}

__device__ __forceinline__ void mma_bf16(float* d, const uint32_t* a, uint32_t b0, uint32_t b1) {
    asm volatile("mma.sync.aligned.m16n8k16.row.col.f32.bf16.bf16.f32 "
                 "{%0,%1,%2,%3}, {%4,%5,%6,%7}, {%8,%9}, {%0,%1,%2,%3};"
                 : "+f"(d[0]), "+f"(d[1]), "+f"(d[2]), "+f"(d[3])
                 : "r"(a[0]), "r"(a[1]), "r"(a[2]), "r"(a[3]), "r"(b0), "r"(b1));
}

// ---------------------------------------------------------------------------
// Kernel 1: g_sw[b,l] = (1e-5 + sum_d x^2)^(1/4)   (sqrt of token weight)
// ---------------------------------------------------------------------------
__global__ void weight_kernel(const float* __restrict__ x) {
    int row  = blockIdx.x * 8 + (threadIdx.x >> 5);
    int lane = threadIdx.x & 31;
    const float4* p = (const float4*)(x + (size_t)row * DDIM);
    float s = 0.f;
#pragma unroll
    for (int i = 0; i < DDIM / 4 / 32; i++) {
        float4 v = p[lane + 32 * i];
        s += v.x * v.x + v.y * v.y + v.z * v.z + v.w * v.w;
    }
#pragma unroll
    for (int o = 16; o; o >>= 1) s += __shfl_xor_sync(0xffffffffu, s, o);
    if (lane == 0) g_sw[row] = sqrtf(sqrtf(1e-5f + s));
}

// ---------------------------------------------------------------------------
// Kernel 2: Yt[b,d,l] = split_bf16( sw[b,l] * x[b,l,d] )  (transposed write)
// ---------------------------------------------------------------------------
__global__ __launch_bounds__(256)
void convert_kernel(const float* __restrict__ x) {
    __shared__ float t[32][33];
    const int b  = blockIdx.z;
    const int d0 = blockIdx.x * 32;
    const int l0 = blockIdx.y * 32;
    const int tx = threadIdx.x & 31;
    const int ty = threadIdx.x >> 5;
    const float* xb = x + (size_t)b * LSEQ * DDIM;

#pragma unroll
    for (int ll = 0; ll < 4; ll++) {
        int l = l0 + ty + ll * 8;
        t[ty + ll * 8][tx] = xb[(size_t)l * DDIM + d0 + tx] * g_sw[b * LSEQ + l];
    }
    __syncthreads();
    size_t base = ((size_t)b * DDIM) * LSEQ;
#pragma unroll
    for (int ll = 0; ll < 4; ll++) {
        int d = d0 + ty + ll * 8;
        int l = l0 + tx;
        float y = t[tx][ty + ll * 8];
        __nv_bfloat16 hi = __float2bfloat16(y);
        float lo = y - __bfloat162float(hi);
        g_yhi[base + (size_t)d * LSEQ + l] = hi;
        g_ylo[base + (size_t)d * LSEQ + l] = __float2bfloat16(lo);
    }
}

// ---------------------------------------------------------------------------
// Kernel 3: per-batch C = Yt Yt^T, bf16 HMMA, 3-pass compensation, symmetric.
// 128x128 tile, BK=32, cp.async double buffer, swizzled smem, 8 warps (4x2).
// ---------------------------------------------------------------------------
#define STAGE_BYTES 32768
#define SMEM_NEED   (2 * STAGE_BYTES + 1024)

__global__ __launch_bounds__(256)
void gram_mma_kernel(float* __restrict__ out) {
    extern __shared__ char dyn[];
    const int tj = blockIdx.x, ti = blockIdx.y, b = blockIdx.z;
    if (tj < ti) return;

    const int tid = threadIdx.x, lane = tid & 31, wid = tid >> 5;
    const int wm = wid & 3, wn = wid >> 2;

    uint32_t raw   = smem_u32(dyn);
    uint32_t sbase = (raw + 1023u) & ~1023u;
    float (*T)[132] = (float (*)[132])(dyn + (sbase - raw));   // epilogue staging

    const size_t ybase = (size_t)b * DDIM * LSEQ;
    const char* src[4] = {
        (const char*)(g_yhi + ybase + (size_t)ti * 128 * LSEQ),   // A hi
        (const char*)(g_ylo + ybase + (size_t)ti * 128 * LSEQ),   // A lo
        (const char*)(g_yhi + ybase + (size_t)tj * 128 * LSEQ),   // B hi
        (const char*)(g_ylo + ybase + (size_t)tj * 128 * LSEQ)};  // B lo

    float acc[2][8][4];
#pragma unroll
    for (int i = 0; i < 2; i++)
#pragma unroll
        for (int j = 0; j < 8; j++)
#pragma unroll
            for (int k = 0; k < 4; k++) acc[i][j][k] = 0.f;

    const int lrow = tid >> 2;          // 0..63
    const int lc   = tid & 3;           // 16B chunk within 64B row

    // prefetch chunk 0
#pragma unroll
    for (int t = 0; t < 4; t++)
#pragma unroll
        for (int i = 0; i < 2; i++) {
            int r = lrow + i * 64;
            CP_ASYNC16(sbase + t * 8192 + sw_off(r, lc),
                       src[t] + (size_t)r * (LSEQ * 2) + lc * 16);
        }
    CP_COMMIT();

    const int arow = wm * 32 + ((lane >> 3) & 1) * 8 + (lane & 7);
    const int brow = wn * 64 + ((lane >> 3) & 1) * 8 + (lane & 7);
    const int NCH = LSEQ / 32;          // 16

    for (int it = 0; it < NCH; it++) {
        if (it + 1 < NCH) {
            uint32_t sb = sbase + ((it + 1) & 1) * STAGE_BYTES;
            int koff = (it + 1) * 64;
#pragma unroll
            for (int t = 0; t < 4; t++)
#pragma unroll
                for (int i = 0; i < 2; i++) {
                    int r = lrow + i * 64;
                    CP_ASYNC16(sb + t * 8192 + sw_off(r, lc),
                               src[t] + (size_t)r * (LSEQ * 2) + koff + lc * 16);
                }
            CP_COMMIT();
            CP_WAIT1();
        } else {
            CP_WAIT0();
        }
        __syncthreads();

        uint32_t sb = sbase + (it & 1) * STAGE_BYTES;
#pragma unroll
        for (int ks = 0; ks < 2; ks++) {
            const int ac = ks * 2 + (lane >> 4);
            uint32_t ah[2][4], bh[4][4];
            ldsm4(ah[0], sb + sw_off(arow, ac));
            ldsm4(ah[1], sb + sw_off(arow + 16, ac));
#pragma unroll
            for (int q = 0; q < 4; q++)
                ldsm4(bh[q], sb + 16384 + sw_off(brow + q * 16, ac));
            // pass 1: hi * hi
#pragma unroll
            for (int mt = 0; mt < 2; mt++)
#pragma unroll
                for (int q = 0; q < 4; q++) {
                    mma_bf16(acc[mt][2 * q],     ah[mt], bh[q][0], bh[q][2]);
                    mma_bf16(acc[mt][2 * q + 1], ah[mt], bh[q][1], bh[q][3]);
                }
            // pass 2: hi * lo
            uint32_t bl[4][4];
#pragma unroll
            for (int q = 0; q < 4; q++)
                ldsm4(bl[q], sb + 24576 + sw_off(brow + q * 16, ac));
#pragma unroll
            for (int mt = 0; mt < 2; mt++)
#pragma unroll
                for (int q = 0; q < 4; q++) {
                    mma_bf16(acc[mt][2 * q],     ah[mt], bl[q][0], bl[q][2]);
                    mma_bf16(acc[mt][2 * q + 1], ah[mt], bl[q][1], bl[q][3]);
                }
            // pass 3: lo * hi
            uint32_t al[2][4];
            ldsm4(al[0], sb + 8192 + sw_off(arow, ac));
            ldsm4(al[1], sb + 8192 + sw_off(arow + 16, ac));
#pragma unroll
            for (int mt = 0; mt < 2; mt++)
#pragma unroll
                for (int q = 0; q < 4; q++) {
                    mma_bf16(acc[mt][2 * q],     al[mt], bh[q][0], bh[q][2]);
                    mma_bf16(acc[mt][2 * q + 1], al[mt], bh[q][1], bh[q][3]);
                }
        }
        __syncthreads();
    }

    float* ob = out + (size_t)b * DDIM * DDIM;

    // direct (upper/diagonal) write
    const int r0 = ti * 128 + wm * 32 + (lane >> 2);
    const int c0 = tj * 128 + wn * 64 + (lane & 3) * 2;
#pragma unroll
    for (int mt = 0; mt < 2; mt++)
#pragma unroll
        for (int q = 0; q < 8; q++) {
            int r = r0 + mt * 16;
            int c = c0 + q * 8;
            *(float2*)(ob + (size_t)r * DDIM + c)       = make_float2(acc[mt][q][0], acc[mt][q][1]);
            *(float2*)(ob + (size_t)(r + 8) * DDIM + c) = make_float2(acc[mt][q][2], acc[mt][q][3]);
        }

    // mirror (lower) write via smem transpose, 32-col groups, coalesced stores
    if (ti != tj) {
#pragma unroll 1
        for (int g = 0; g < 4; g++) {
            __syncthreads();
            if (wn == (g >> 1)) {
#pragma unroll
                for (int mt = 0; mt < 2; mt++)
#pragma unroll
                    for (int qq = 0; qq < 4; qq++) {
                        int q    = (g & 1) * 4 + qq;
                        int lcol = qq * 8 + (lane & 3) * 2;
                        int grow = wm * 32 + mt * 16 + (lane >> 2);
                        T[lcol][grow]         = acc[mt][q][0];
                        T[lcol + 1][grow]     = acc[mt][q][1];
                        T[lcol][grow + 8]     = acc[mt][q][2];
                        T[lcol + 1][grow + 8] = acc[mt][q][3];
                    }
            }
            __syncthreads();
#pragma unroll
            for (int u = 0; u < 4; u++) {
                int v  = tid + u * 256;
                int rr = v >> 5;
                int cc = (v & 31) * 4;
                float4 val = *(float4*)&T[rr][cc];
                *(float4*)(ob + (size_t)(tj * 128 + g * 32 + rr) * DDIM + ti * 128 + cc) = val;
            }
        }
    }
}

// ---------------------------------------------------------------------------
extern "C" void kernel_launch(void* const* d_in, const int* in_sizes, int n_in,
                              void* d_out, int out_size) {
    const float* x = (const float*)d_in[0];
    float* out = (float*)d_out;

    weight_kernel<<<BATCH * LSEQ / 8, 256>>>(x);

    dim3 cgrid(DDIM / 32, LSEQ / 32, BATCH);
    convert_kernel<<<cgrid, 256>>>(x);

    cudaFuncSetAttribute(gram_mma_kernel, cudaFuncAttributeMaxDynamicSharedMemorySize, SMEM_NEED);
    dim3 ggrid(DDIM / 128, DDIM / 128, BATCH);   // (6, 6, 32), lower tiles early-exit
    gram_mma_kernel<<<ggrid, 256, SMEM_NEED>>>(out);
}

// round 4
// speedup vs baseline: 3.0027x; 2.1186x over previous
#include <cuda_runtime.h>
#include <cuda_fp16.h>
#include <cstdint>
#include <math.h>

#define BATCH 32
#define LSEQ  512
#define DDIM  768

// scratch (no cudaMalloc allowed): Yt[b][d][l] = fp16( sqrt(w[b,l]) * x[b,l,d] ), K(=l)-major
__device__ __align__(1024) __half g_yt[(size_t)BATCH * DDIM * LSEQ];

// ---------------------------------------------------------------------------
__device__ __forceinline__ uint32_t smem_u32(const void* p) {
    uint32_t a;
    asm("{ .reg .u64 t; cvta.to.shared.u64 t, %1; cvt.u32.u64 %0, t; }" : "=r"(a) : "l"(p));
    return a;
}

// 128 logical rows x 32 halfs (64B); pack 2 rows per 128B physical row, XOR swizzle
__device__ __forceinline__ uint32_t sw_off(int r, int c) {
    uint32_t pr = (uint32_t)r >> 1;
    uint32_t ch = (uint32_t)(((r & 1) << 2) + c) ^ (pr & 7u);
    return pr * 128u + ch * 16u;
}

#define CP_ASYNC16(dst, src) \
    asm volatile("cp.async.cg.shared.global [%0], [%1], 16;" :: "r"(dst), "l"(src))
#define CP_COMMIT() asm volatile("cp.async.commit_group;" ::: "memory")
#define CP_WAIT2()  asm volatile("cp.async.wait_group 2;" ::: "memory")
#define CP_WAIT0()  asm volatile("cp.async.wait_group 0;" ::: "memory")

__device__ __forceinline__ void ldsm4(uint32_t* r, uint32_t a) {
    asm volatile("ldmatrix.sync.aligned.m8n8.x4.shared.b16 {%0,%1,%2,%3}, [%4];"
                 : "=r"(r[0]), "=r"(r[1]), "=r"(r[2]), "=r"(r[3]) : "r"(a));
}

__device__ __forceinline__ void mma_f16(float* d, const uint32_t* a, uint32_t b0, uint32_t b1) {
    asm volatile("mma.sync.aligned.m16n8k16.row.col.f32.f16.f16.f32 "
                 "{%0,%1,%2,%3}, {%4,%5,%6,%7}, {%8,%9}, {%0,%1,%2,%3};"
                 : "+f"(d[0]), "+f"(d[1]), "+f"(d[2]), "+f"(d[3])
                 : "r"(a[0]), "r"(a[1]), "r"(a[2]), "r"(a[3]), "r"(b0), "r"(b1));
}

// ---------------------------------------------------------------------------
// Prep: fused weight + scale + transpose + fp16 convert.
// Block = (32 tokens of one batch). Phase 1 computes norms (warming L1),
// phase 2 re-reads (L1 hits), scales, transposes via smem, writes Yt.
// ---------------------------------------------------------------------------
__global__ __launch_bounds__(256)
void prep_kernel(const float* __restrict__ x) {
    __shared__ float sw[32];
    __shared__ float t[32][33];
    const int b  = blockIdx.y;
    const int l0 = blockIdx.x * 32;
    const int tid  = threadIdx.x;
    const int lane = tid & 31;
    const int wid  = tid >> 5;

    // phase 1: token norms (4 rows per warp)
#pragma unroll
    for (int i = 0; i < 4; i++) {
        int l = l0 + wid * 4 + i;
        const float4* p = (const float4*)(x + ((size_t)b * LSEQ + l) * DDIM);
        float s = 0.f;
#pragma unroll
        for (int j = 0; j < DDIM / 128; j++) {
            float4 v = p[lane + 32 * j];
            s += v.x * v.x + v.y * v.y + v.z * v.z + v.w * v.w;
        }
#pragma unroll
        for (int o = 16; o; o >>= 1) s += __shfl_xor_sync(0xffffffffu, s, o);
        if (lane == 0) sw[wid * 4 + i] = sqrtf(sqrtf(1e-5f + s));
    }
    __syncthreads();

    // phase 2: scale + transpose + fp16 write
    const int tx = lane, ty = wid;
    const float* xb = x + (size_t)b * LSEQ * DDIM;
    __half* yb = g_yt + (size_t)b * DDIM * LSEQ;
#pragma unroll 1
    for (int dt = 0; dt < DDIM / 32; dt++) {
        int d0 = dt * 32;
#pragma unroll
        for (int k = 0; k < 4; k++)
            t[ty + 8 * k][tx] = xb[(size_t)(l0 + ty + 8 * k) * DDIM + d0 + tx] * sw[ty + 8 * k];
        __syncthreads();
#pragma unroll
        for (int k = 0; k < 4; k++)
            yb[(size_t)(d0 + ty + 8 * k) * LSEQ + l0 + tx] = __float2half(t[tx][ty + 8 * k]);
        __syncthreads();
    }
}

// ---------------------------------------------------------------------------
// Gram: per-batch C = Yt Yt^T, fp16 HMMA single pass, symmetric tiles.
// 128x128 tile, BK=32, 3-stage cp.async pipeline, swizzled smem, 8 warps (4x2).
// ---------------------------------------------------------------------------
#define STAGE_BYTES 16384
#define NSTAGE 3
#define SMEM_NEED (NSTAGE * STAGE_BYTES + 1024)

__global__ __launch_bounds__(256)
void gram_mma_kernel(float* __restrict__ out) {
    extern __shared__ char dyn[];
    const int tj = blockIdx.x, ti = blockIdx.y, b = blockIdx.z;
    if (tj < ti) return;

    const int tid = threadIdx.x, lane = tid & 31, wid = tid >> 5;
    const int wm = wid & 3, wn = wid >> 2;

    uint32_t raw   = smem_u32(dyn);
    uint32_t sbase = (raw + 1023u) & ~1023u;
    float (*T)[132] = (float (*)[132])(dyn + (sbase - raw));   // epilogue staging (aliases stages)

    const size_t ybase = (size_t)b * DDIM * LSEQ;
    const char* srcA = (const char*)(g_yt + ybase + (size_t)ti * 128 * LSEQ);
    const char* srcB = (const char*)(g_yt + ybase + (size_t)tj * 128 * LSEQ);

    float acc[2][8][4];
#pragma unroll
    for (int i = 0; i < 2; i++)
#pragma unroll
        for (int j = 0; j < 8; j++)
#pragma unroll
            for (int k = 0; k < 4; k++) acc[i][j][k] = 0.f;

    const int lrow = tid >> 2;          // 0..63
    const int lc   = tid & 3;           // 16B chunk within 64B logical row

    const int NCH = LSEQ / 32;          // 16

    // issue stage s for chunk it
#define ISSUE(st, it_)                                                                  \
    do {                                                                                \
        uint32_t sb_ = sbase + (st) * STAGE_BYTES;                                      \
        int ko_ = (it_) * 64;                                                           \
        _Pragma("unroll")                                                               \
        for (int i_ = 0; i_ < 2; i_++) {                                                \
            int r_ = lrow + 64 * i_;                                                    \
            CP_ASYNC16(sb_ + sw_off(r_, lc),        srcA + (size_t)r_ * (LSEQ * 2) + ko_ + lc * 16); \
            CP_ASYNC16(sb_ + 8192 + sw_off(r_, lc), srcB + (size_t)r_ * (LSEQ * 2) + ko_ + lc * 16); \
        }                                                                               \
    } while (0)

    ISSUE(0, 0); CP_COMMIT();
    ISSUE(1, 1); CP_COMMIT();

    const int arow = wm * 32 + ((lane >> 3) & 1) * 8 + (lane & 7);
    const int brow = wn * 64 + ((lane >> 3) & 1) * 8 + (lane & 7);

    for (int it = 0; it < NCH; it++) {
        if (it + 2 < NCH) {
            ISSUE((it + 2) % NSTAGE, it + 2);
            CP_COMMIT();
            CP_WAIT2();
        } else {
            CP_WAIT0();
        }
        __syncthreads();

        uint32_t sb = sbase + (it % NSTAGE) * STAGE_BYTES;
#pragma unroll
        for (int ks = 0; ks < 2; ks++) {
            const int ac = ks * 2 + (lane >> 4);
            uint32_t ah[2][4], bh[4][4];
            ldsm4(ah[0], sb + sw_off(arow, ac));
            ldsm4(ah[1], sb + sw_off(arow + 16, ac));
#pragma unroll
            for (int q = 0; q < 4; q++)
                ldsm4(bh[q], sb + 8192 + sw_off(brow + q * 16, ac));
#pragma unroll
            for (int mt = 0; mt < 2; mt++)
#pragma unroll
                for (int q = 0; q < 4; q++) {
                    mma_f16(acc[mt][2 * q],     ah[mt], bh[q][0], bh[q][2]);
                    mma_f16(acc[mt][2 * q + 1], ah[mt], bh[q][1], bh[q][3]);
                }
        }
        __syncthreads();
    }

    float* ob = out + (size_t)b * DDIM * DDIM;

    // direct (upper/diagonal) write
    const int r0 = ti * 128 + wm * 32 + (lane >> 2);
    const int c0 = tj * 128 + wn * 64 + (lane & 3) * 2;
#pragma unroll
    for (int mt = 0; mt < 2; mt++)
#pragma unroll
        for (int q = 0; q < 8; q++) {
            int r = r0 + mt * 16;
            int c = c0 + q * 8;
            *(float2*)(ob + (size_t)r * DDIM + c)       = make_float2(acc[mt][q][0], acc[mt][q][1]);
            *(float2*)(ob + (size_t)(r + 8) * DDIM + c) = make_float2(acc[mt][q][2], acc[mt][q][3]);
        }

    // mirror (lower) write via smem transpose, 32-col groups, coalesced stores
    if (ti != tj) {
#pragma unroll 1
        for (int g = 0; g < 4; g++) {
            __syncthreads();
            if (wn == (g >> 1)) {
#pragma unroll
                for (int mt = 0; mt < 2; mt++)
#pragma unroll
                    for (int qq = 0; qq < 4; qq++) {
                        int q    = (g & 1) * 4 + qq;
                        int lcol = qq * 8 + (lane & 3) * 2;
                        int grow = wm * 32 + mt * 16 + (lane >> 2);
                        T[lcol][grow]         = acc[mt][q][0];
                        T[lcol + 1][grow]     = acc[mt][q][1];
                        T[lcol][grow + 8]     = acc[mt][q][2];
                        T[lcol + 1][grow + 8] = acc[mt][q][3];
                    }
            }
            __syncthreads();
#pragma unroll
            for (int u = 0; u < 4; u++) {
                int v  = tid + u * 256;
                int rr = v >> 5;
                int cc = (v & 31) * 4;
                float4 val = *(float4*)&T[rr][cc];
                *(float4*)(ob + (size_t)(tj * 128 + g * 32 + rr) * DDIM + ti * 128 + cc) = val;
            }
        }
    }
}

// ---------------------------------------------------------------------------
extern "C" void kernel_launch(void* const* d_in, const int* in_sizes, int n_in,
                              void* d_out, int out_size) {
    const float* x = (const float*)d_in[0];
    float* out = (float*)d_out;

    dim3 pgrid(LSEQ / 32, BATCH);
    prep_kernel<<<pgrid, 256>>>(x);

    cudaFuncSetAttribute(gram_mma_kernel, cudaFuncAttributeMaxDynamicSharedMemorySize, SMEM_NEED);
    dim3 ggrid(DDIM / 128, DDIM / 128, BATCH);   // (6, 6, 32), lower tiles early-exit
    gram_mma_kernel<<<ggrid, 256, SMEM_NEED>>>(out);
}